// round 5
// baseline (speedup 1.0000x reference)
#include <cuda_runtime.h>
#include <cuda_bf16.h>

// B=8, D=3, N=M=4096 fused chamfer + MSE.
// d_ij = n1_i + (n2_j - 2*dot) computed as a 3-FMA2 chain with j-coords
// premultiplied by -2 in smem (seeded by n2). f32x2 lanes carry a j-PAIR.
// Kernel 1: 4096 blocks = b(8) x dir(2) x isplit(16) x jsplit(16), 256 thr,
//   IPER=2 i-points/thread. Inner per j-pair: 2 LDS.128 + 6 FMA2 + 4 FMNMX.
// Kernel 2: 128 blocks: min over 16 j-chunks + partial sums (deterministic).
// Kernel 3: 1 warp: means + MSE.

#define NPTS    4096
#define SPLITS  16           // j-splits
#define JCHUNK  256          // NPTS / SPLITS
#define JPAIRS  (JCHUNK / 2)
#define ISPLITS 16
#define TPB     256
#define IPER    2            // TPB*IPER = 512 = NPTS/ISPLITS

__device__ float g_partial[8 * 2 * SPLITS * NPTS];   // 4 MB scratch
__device__ float g_sums[16 * 8];

typedef unsigned long long u64;

__device__ __forceinline__ u64 pack2(float lo, float hi) {
    u64 r; asm("mov.b64 %0, {%1, %2};" : "=l"(r) : "f"(lo), "f"(hi)); return r;
}
__device__ __forceinline__ u64 fma2(u64 a, u64 b, u64 c) {
    u64 r; asm("fma.rn.f32x2 %0, %1, %2, %3;" : "=l"(r) : "l"(a), "l"(b), "l"(c)); return r;
}
__device__ __forceinline__ void unpack2(u64 v, float& lo, float& hi) {
    asm("mov.b64 {%0, %1}, %2;" : "=f"(lo), "=f"(hi) : "l"(v));
}
__device__ __forceinline__ void lds_v2u64(u64& a, u64& b, const void* p) {
    u64 g = __cvta_generic_to_shared(p);
    asm("ld.shared.v2.b64 {%0, %1}, [%2];" : "=l"(a), "=l"(b) : "l"(g));
}

__global__ __launch_bounds__(TPB, 4)
void chamfer_partial_kernel(const float* __restrict__ points,
                            const float* __restrict__ points_trans) {
    const int blk    = blockIdx.x;              // 0..4095
    const int s      = blk & (SPLITS - 1);      // j-chunk
    const int isplit = (blk >> 4) & (ISPLITS - 1);
    const int dir    = (blk >> 8) & 1;
    const int b      = blk >> 9;

    const float* p1b = (dir ? points_trans : points) + b * 3 * NPTS;
    const float* p2b = (dir ? points : points_trans) + b * 3 * NPTS;

    // smem per j-pair: A = {-2x0,-2x1,-2y0,-2y1}, B = {-2z0,-2z1, n0, n1}
    __shared__ __align__(16) float sjA[JPAIRS * 4];
    __shared__ __align__(16) float sjB[JPAIRS * 4];

    const int t = threadIdx.x;

    if (t < JPAIRS) {
        int j = s * JCHUNK + 2 * t;
        float x0 = p2b[j],            x1 = p2b[j + 1];
        float y0 = p2b[NPTS + j],     y1 = p2b[NPTS + j + 1];
        float z0 = p2b[2 * NPTS + j], z1 = p2b[2 * NPTS + j + 1];
        sjA[4 * t + 0] = -2.0f * x0; sjA[4 * t + 1] = -2.0f * x1;
        sjA[4 * t + 2] = -2.0f * y0; sjA[4 * t + 3] = -2.0f * y1;
        sjB[4 * t + 0] = -2.0f * z0; sjB[4 * t + 1] = -2.0f * z1;
        sjB[4 * t + 2] = x0 * x0 + y0 * y0 + z0 * z0;
        sjB[4 * t + 3] = x1 * x1 + y1 * y1 + z1 * z1;
    }

    const int ibase = isplit * (TPB * IPER);
    u64 Xb[IPER], Yb[IPER], Zb[IPER];
    float n1[IPER];
#pragma unroll
    for (int k = 0; k < IPER; ++k) {
        int i = ibase + k * TPB + t;
        float x = p1b[i], y = p1b[NPTS + i], z = p1b[2 * NPTS + i];
        n1[k] = x * x + y * y + z * z;
        Xb[k] = pack2(x, x);
        Yb[k] = pack2(y, y);
        Zb[k] = pack2(z, z);
    }

    float mnlo[IPER], mnhi[IPER];
#pragma unroll
    for (int k = 0; k < IPER; ++k) { mnlo[k] = 3.0e38f; mnhi[k] = 3.0e38f; }

    __syncthreads();

#pragma unroll 4
    for (int jp = 0; jp < JPAIRS; ++jp) {
        u64 xj, yj, zj, nj;
        lds_v2u64(xj, yj, &sjA[4 * jp]);   // (-2x0,-2x1), (-2y0,-2y1)
        lds_v2u64(zj, nj, &sjB[4 * jp]);   // (-2z0,-2z1), (n0,n1)
#pragma unroll
        for (int k = 0; k < IPER; ++k) {
            u64 d = fma2(Zb[k], zj, nj);   // n2 - 2 z1 z2
            d = fma2(Yb[k], yj, d);
            d = fma2(Xb[k], xj, d);        // n2 - 2*dot for (j0, j1)
            float dlo, dhi;
            unpack2(d, dlo, dhi);
            mnlo[k] = fminf(mnlo[k], dlo);
            mnhi[k] = fminf(mnhi[k], dhi);
        }
    }

    float* dst = g_partial + ((size_t)((b * 2 + dir) * SPLITS + s)) * NPTS;
#pragma unroll
    for (int k = 0; k < IPER; ++k) {
        int i = ibase + k * TPB + t;
        dst[i] = n1[k] + fminf(mnlo[k], mnhi[k]);
    }
}

__global__ __launch_bounds__(TPB)
void chamfer_reduce_kernel() {
    const int bd     = blockIdx.x >> 3;      // 0..15
    const int ichunk = blockIdx.x & 7;       // 0..7 (512 i each)
    const int t      = threadIdx.x;

    const float* base = g_partial + (size_t)bd * SPLITS * NPTS;
    float sum = 0.0f;
#pragma unroll
    for (int k = 0; k < 2; ++k) {
        int i = ichunk * 512 + k * TPB + t;
        float m = 3.0e38f;
#pragma unroll
        for (int s2 = 0; s2 < SPLITS; ++s2)
            m = fminf(m, base[s2 * NPTS + i]);
        sum += m;
    }

    __shared__ float red[TPB];
    red[t] = sum;
    __syncthreads();
    for (int off = TPB / 2; off >= 32; off >>= 1) {
        if (t < off) red[t] += red[t + off];
        __syncthreads();
    }
    if (t < 32) {
        float v = red[t];
#pragma unroll
        for (int off = 16; off > 0; off >>= 1)
            v += __shfl_xor_sync(0xFFFFFFFFu, v, off);
        if (t == 0) g_sums[bd * 8 + ichunk] = v;
    }
}

__global__ void mse_kernel(const float* __restrict__ pred, float* __restrict__ out) {
    int t = threadIdx.x;
    float v = 0.0f;
    if (t < 16) {
        float s = 0.0f;
#pragma unroll
        for (int c = 0; c < 8; ++c) s += g_sums[t * 8 + c];
        float cham = s * (1.0f / (float)NPTS);
        float d = pred[t] - cham;
        v = d * d;
    }
#pragma unroll
    for (int off = 16; off > 0; off >>= 1)
        v += __shfl_xor_sync(0xFFFFFFFFu, v, off);
    if (t == 0) out[0] = v * (1.0f / 16.0f);
}

extern "C" void kernel_launch(void* const* d_in, const int* in_sizes, int n_in,
                              void* d_out, int out_size) {
    const float* pred         = (const float*)d_in[0];   // [8,2]
    const float* points       = (const float*)d_in[1];   // [8,3,4096]
    const float* points_trans = (const float*)d_in[2];   // [8,3,4096]
    float* out = (float*)d_out;

    chamfer_partial_kernel<<<8 * 2 * ISPLITS * SPLITS, TPB>>>(points, points_trans);
    chamfer_reduce_kernel<<<128, TPB>>>();
    mse_kernel<<<1, 32>>>(pred, out);
}

// round 7
// speedup vs baseline: 1.6369x; 1.6369x over previous
#include <cuda_runtime.h>
#include <cuda_bf16.h>

// B=8, D=3, N=M=4096 fused chamfer + MSE.
// d_ij = n1_i + (n2_j - 2*dot): 3-FMA2 chain, j coords premultiplied by -2,
// chain seeded with n2. f32x2 lanes carry a j-PAIR.
// Kernel 1: 4096 blocks = b(8) x dir(2) x isplit(4) x jsplit(64), 256 thr,
//   IPER=4 -> block covers 1024 i x 64 j. 4*256*4 = 4096 = NPTS exactly.
//   Inner per j-pair per thread: 2 LDS.128 + 12 FMA2 + 8 FMNMX.
// Kernel 2: 128 blocks: min over 64 j-chunks + partial sums (deterministic).
// Kernel 3: 1 warp: means + MSE.

#define NPTS    4096
#define SPLITS  64           // j-splits
#define JCHUNK  64           // NPTS / SPLITS
#define JPAIRS  (JCHUNK / 2) // 32
#define ISPLITS 4
#define TPB     256
#define IPER    4            // ISPLITS*TPB*IPER = 4096 = NPTS  (exact cover)

__device__ float g_partial[8 * 2 * SPLITS * NPTS];   // 16 MB scratch
__device__ float g_sums[16 * 8];

typedef unsigned long long u64;

__device__ __forceinline__ u64 pack2(float lo, float hi) {
    u64 r; asm("mov.b64 %0, {%1, %2};" : "=l"(r) : "f"(lo), "f"(hi)); return r;
}
__device__ __forceinline__ u64 fma2(u64 a, u64 b, u64 c) {
    u64 r; asm("fma.rn.f32x2 %0, %1, %2, %3;" : "=l"(r) : "l"(a), "l"(b), "l"(c)); return r;
}
__device__ __forceinline__ void unpack2(u64 v, float& lo, float& hi) {
    asm("mov.b64 {%0, %1}, %2;" : "=f"(lo), "=f"(hi) : "l"(v));
}
__device__ __forceinline__ void lds_v2u64(u64& a, u64& b, const void* p) {
    u64 g = __cvta_generic_to_shared(p);
    asm("ld.shared.v2.b64 {%0, %1}, [%2];" : "=l"(a), "=l"(b) : "l"(g));
}

__global__ __launch_bounds__(TPB, 4)
void chamfer_partial_kernel(const float* __restrict__ points,
                            const float* __restrict__ points_trans) {
    const int blk    = blockIdx.x;              // 0..4095
    const int s      = blk & (SPLITS - 1);      // bits [0,6)
    const int isplit = (blk >> 6) & (ISPLITS - 1);
    const int dir    = (blk >> 8) & 1;
    const int b      = blk >> 9;

    const float* p1b = (dir ? points_trans : points) + b * 3 * NPTS;
    const float* p2b = (dir ? points : points_trans) + b * 3 * NPTS;

    // smem per j-pair: A = {-2x0,-2x1,-2y0,-2y1}, B = {-2z0,-2z1, n0, n1}
    __shared__ __align__(16) float sjA[JPAIRS * 4];
    __shared__ __align__(16) float sjB[JPAIRS * 4];

    const int t = threadIdx.x;

    if (t < JPAIRS) {
        int j = s * JCHUNK + 2 * t;
        float x0 = p2b[j],            x1 = p2b[j + 1];
        float y0 = p2b[NPTS + j],     y1 = p2b[NPTS + j + 1];
        float z0 = p2b[2 * NPTS + j], z1 = p2b[2 * NPTS + j + 1];
        sjA[4 * t + 0] = -2.0f * x0; sjA[4 * t + 1] = -2.0f * x1;
        sjA[4 * t + 2] = -2.0f * y0; sjA[4 * t + 3] = -2.0f * y1;
        sjB[4 * t + 0] = -2.0f * z0; sjB[4 * t + 1] = -2.0f * z1;
        sjB[4 * t + 2] = x0 * x0 + y0 * y0 + z0 * z0;
        sjB[4 * t + 3] = x1 * x1 + y1 * y1 + z1 * z1;
    }

    const int ibase = isplit * (TPB * IPER);    // 0,1024,2048,3072
    u64 Xb[IPER], Yb[IPER], Zb[IPER];
    float n1[IPER];
#pragma unroll
    for (int k = 0; k < IPER; ++k) {
        int i = ibase + k * TPB + t;            // < 4096 always
        float x = p1b[i], y = p1b[NPTS + i], z = p1b[2 * NPTS + i];
        n1[k] = x * x + y * y + z * z;
        Xb[k] = pack2(x, x);
        Yb[k] = pack2(y, y);
        Zb[k] = pack2(z, z);
    }

    float mnlo[IPER], mnhi[IPER];
#pragma unroll
    for (int k = 0; k < IPER; ++k) { mnlo[k] = 3.0e38f; mnhi[k] = 3.0e38f; }

    __syncthreads();

#pragma unroll 8
    for (int jp = 0; jp < JPAIRS; ++jp) {
        u64 xj, yj, zj, nj;
        lds_v2u64(xj, yj, &sjA[4 * jp]);   // (-2x0,-2x1), (-2y0,-2y1)
        lds_v2u64(zj, nj, &sjB[4 * jp]);   // (-2z0,-2z1), (n0,n1)
#pragma unroll
        for (int k = 0; k < IPER; ++k) {
            u64 d = fma2(Zb[k], zj, nj);   // n2 - 2 z1 z2
            d = fma2(Yb[k], yj, d);
            d = fma2(Xb[k], xj, d);        // n2 - 2*dot for (j0, j1)
            float dlo, dhi;
            unpack2(d, dlo, dhi);
            mnlo[k] = fminf(mnlo[k], dlo);
            mnhi[k] = fminf(mnhi[k], dhi);
        }
    }

    float* dst = g_partial + ((size_t)((b * 2 + dir) * SPLITS + s)) * NPTS;
#pragma unroll
    for (int k = 0; k < IPER; ++k) {
        int i = ibase + k * TPB + t;
        dst[i] = n1[k] + fminf(mnlo[k], mnhi[k]);
    }
}

__global__ __launch_bounds__(TPB)
void chamfer_reduce_kernel() {
    const int bd     = blockIdx.x >> 3;      // 0..15
    const int ichunk = blockIdx.x & 7;       // 0..7 (512 i each)
    const int t      = threadIdx.x;

    const float* base = g_partial + (size_t)bd * SPLITS * NPTS;
    float sum = 0.0f;
#pragma unroll
    for (int k = 0; k < 2; ++k) {
        int i = ichunk * 512 + k * TPB + t;
        float m = 3.0e38f;
#pragma unroll 16
        for (int s2 = 0; s2 < SPLITS; ++s2)
            m = fminf(m, base[s2 * NPTS + i]);
        sum += m;
    }

    __shared__ float red[TPB];
    red[t] = sum;
    __syncthreads();
    for (int off = TPB / 2; off >= 32; off >>= 1) {
        if (t < off) red[t] += red[t + off];
        __syncthreads();
    }
    if (t < 32) {
        float v = red[t];
#pragma unroll
        for (int off = 16; off > 0; off >>= 1)
            v += __shfl_xor_sync(0xFFFFFFFFu, v, off);
        if (t == 0) g_sums[bd * 8 + ichunk] = v;
    }
}

__global__ void mse_kernel(const float* __restrict__ pred, float* __restrict__ out) {
    int t = threadIdx.x;
    float v = 0.0f;
    if (t < 16) {
        float s = 0.0f;
#pragma unroll
        for (int c = 0; c < 8; ++c) s += g_sums[t * 8 + c];
        float cham = s * (1.0f / (float)NPTS);
        float d = pred[t] - cham;
        v = d * d;
    }
#pragma unroll
    for (int off = 16; off > 0; off >>= 1)
        v += __shfl_xor_sync(0xFFFFFFFFu, v, off);
    if (t == 0) out[0] = v * (1.0f / 16.0f);
}

extern "C" void kernel_launch(void* const* d_in, const int* in_sizes, int n_in,
                              void* d_out, int out_size) {
    const float* pred         = (const float*)d_in[0];   // [8,2]
    const float* points       = (const float*)d_in[1];   // [8,3,4096]
    const float* points_trans = (const float*)d_in[2];   // [8,3,4096]
    float* out = (float*)d_out;

    chamfer_partial_kernel<<<8 * 2 * ISPLITS * SPLITS, TPB>>>(points, points_trans);
    chamfer_reduce_kernel<<<128, TPB>>>();
    mse_kernel<<<1, 32>>>(pred, out);
}

// round 9
// speedup vs baseline: 1.7072x; 1.0429x over previous
#include <cuda_runtime.h>
#include <cuda_bf16.h>

// B=8, D=3, N=M=4096 fused chamfer + MSE.
// d_ij = n1_i + (n2_j - 2*dot): 3-FMA2 chain, j coords premultiplied by -2,
// chain seeded with n2. f32x2 lanes carry a j-PAIR.
// All GMEM access is float4 (MLP_p1 3 instead of 12 -> lower cross-CTA
// L1tex-queue spread per the B300 model).
// Kernel 1: 4096 blocks = b(8) x dir(2) x isplit(4) x jsplit(64), 256 thr.
//   Thread t owns i = ibase + 4t..4t+3 (consecutive; float4 loads/stores).
// Kernel 2: 64 blocks, float4 min over 64 j-chunks + partial sums.
// Kernel 3: 1 warp: means + MSE.

#define NPTS    4096
#define SPLITS  64           // j-splits
#define JCHUNK  64           // NPTS / SPLITS
#define JPAIRS  (JCHUNK / 2) // 32
#define ISPLITS 4
#define TPB     256
#define IPER    4            // ISPLITS*TPB*IPER = 4096 = NPTS (exact cover)

__device__ float g_partial[8 * 2 * SPLITS * NPTS];   // 16 MB scratch (L2-resident)
__device__ float g_sums[16 * 4];

typedef unsigned long long u64;

__device__ __forceinline__ u64 pack2(float lo, float hi) {
    u64 r; asm("mov.b64 %0, {%1, %2};" : "=l"(r) : "f"(lo), "f"(hi)); return r;
}
__device__ __forceinline__ u64 fma2(u64 a, u64 b, u64 c) {
    u64 r; asm("fma.rn.f32x2 %0, %1, %2, %3;" : "=l"(r) : "l"(a), "l"(b), "l"(c)); return r;
}
__device__ __forceinline__ void unpack2(u64 v, float& lo, float& hi) {
    asm("mov.b64 {%0, %1}, %2;" : "=f"(lo), "=f"(hi) : "l"(v));
}
__device__ __forceinline__ void lds_v2u64(u64& a, u64& b, const void* p) {
    u64 g = __cvta_generic_to_shared(p);
    asm("ld.shared.v2.b64 {%0, %1}, [%2];" : "=l"(a), "=l"(b) : "l"(g));
}

__global__ __launch_bounds__(TPB, 4)
void chamfer_partial_kernel(const float* __restrict__ points,
                            const float* __restrict__ points_trans) {
    const int blk    = blockIdx.x;              // 0..4095
    const int s      = blk & (SPLITS - 1);      // bits [0,6)
    const int isplit = (blk >> 6) & (ISPLITS - 1);
    const int dir    = (blk >> 8) & 1;
    const int b      = blk >> 9;

    const float* p1b = (dir ? points_trans : points) + b * 3 * NPTS;
    const float* p2b = (dir ? points : points_trans) + b * 3 * NPTS;

    // smem per j-pair: A = {-2x0,-2x1,-2y0,-2y1}, B = {-2z0,-2z1, n0, n1}
    __shared__ __align__(16) float sjA[JPAIRS * 4];
    __shared__ __align__(16) float sjB[JPAIRS * 4];

    const int t = threadIdx.x;

    if (t < 16) {                               // 16 thr x 4 j = 64 = JCHUNK
        int j = s * JCHUNK + 4 * t;
        float4 X = *(const float4*)&p2b[j];
        float4 Y = *(const float4*)&p2b[NPTS + j];
        float4 Z = *(const float4*)&p2b[2 * NPTS + j];
        float4* A = (float4*)&sjA[8 * t];
        A[0] = make_float4(-2.f * X.x, -2.f * X.y, -2.f * Y.x, -2.f * Y.y);
        A[1] = make_float4(-2.f * X.z, -2.f * X.w, -2.f * Y.z, -2.f * Y.w);
        float4* Bv = (float4*)&sjB[8 * t];
        Bv[0] = make_float4(-2.f * Z.x, -2.f * Z.y,
                            X.x * X.x + Y.x * Y.x + Z.x * Z.x,
                            X.y * X.y + Y.y * Y.y + Z.y * Z.y);
        Bv[1] = make_float4(-2.f * Z.z, -2.f * Z.w,
                            X.z * X.z + Y.z * Y.z + Z.z * Z.z,
                            X.w * X.w + Y.w * Y.w + Z.w * Z.w);
    }

    // Thread's 4 consecutive i points via 3 x LDG.128 (low MLP_p1).
    const int ib = isplit * (TPB * IPER) + 4 * t;   // < 4096 always
    float4 vx = *(const float4*)&p1b[ib];
    float4 vy = *(const float4*)&p1b[NPTS + ib];
    float4 vz = *(const float4*)&p1b[2 * NPTS + ib];

    float xs[IPER] = {vx.x, vx.y, vx.z, vx.w};
    float ys[IPER] = {vy.x, vy.y, vy.z, vy.w};
    float zs[IPER] = {vz.x, vz.y, vz.z, vz.w};

    u64 Xb[IPER], Yb[IPER], Zb[IPER];
    float n1[IPER];
#pragma unroll
    for (int k = 0; k < IPER; ++k) {
        n1[k] = xs[k] * xs[k] + ys[k] * ys[k] + zs[k] * zs[k];
        Xb[k] = pack2(xs[k], xs[k]);
        Yb[k] = pack2(ys[k], ys[k]);
        Zb[k] = pack2(zs[k], zs[k]);
    }

    float mnlo[IPER], mnhi[IPER];
#pragma unroll
    for (int k = 0; k < IPER; ++k) { mnlo[k] = 3.0e38f; mnhi[k] = 3.0e38f; }

    __syncthreads();

#pragma unroll 8
    for (int jp = 0; jp < JPAIRS; ++jp) {
        u64 xj, yj, zj, nj;
        lds_v2u64(xj, yj, &sjA[4 * jp]);   // (-2x0,-2x1), (-2y0,-2y1)
        lds_v2u64(zj, nj, &sjB[4 * jp]);   // (-2z0,-2z1), (n0,n1)
#pragma unroll
        for (int k = 0; k < IPER; ++k) {
            u64 d = fma2(Zb[k], zj, nj);   // n2 - 2 z1 z2
            d = fma2(Yb[k], yj, d);
            d = fma2(Xb[k], xj, d);        // n2 - 2*dot for (j0, j1)
            float dlo, dhi;
            unpack2(d, dlo, dhi);
            mnlo[k] = fminf(mnlo[k], dlo);
            mnhi[k] = fminf(mnhi[k], dhi);
        }
    }

    float* dst = g_partial + ((size_t)((b * 2 + dir) * SPLITS + s)) * NPTS;
    float4 r;
    r.x = n1[0] + fminf(mnlo[0], mnhi[0]);
    r.y = n1[1] + fminf(mnlo[1], mnhi[1]);
    r.z = n1[2] + fminf(mnlo[2], mnhi[2]);
    r.w = n1[3] + fminf(mnlo[3], mnhi[3]);
    *(float4*)&dst[ib] = r;                 // STG.128
}

__global__ __launch_bounds__(TPB)
void chamfer_reduce_kernel() {
    const int bd = blockIdx.x >> 2;          // 0..15
    const int ic = blockIdx.x & 3;           // 0..3 (1024 i each)
    const int t  = threadIdx.x;

    const float* base = g_partial + (size_t)bd * SPLITS * NPTS;
    const int i = ic * 1024 + 4 * t;

    float4 m = make_float4(3.0e38f, 3.0e38f, 3.0e38f, 3.0e38f);
#pragma unroll 16
    for (int s2 = 0; s2 < SPLITS; ++s2) {
        float4 v = *(const float4*)&base[s2 * NPTS + i];
        m.x = fminf(m.x, v.x); m.y = fminf(m.y, v.y);
        m.z = fminf(m.z, v.z); m.w = fminf(m.w, v.w);
    }
    float sum = (m.x + m.y) + (m.z + m.w);

    __shared__ float red[TPB];
    red[t] = sum;
    __syncthreads();
    for (int off = TPB / 2; off >= 32; off >>= 1) {
        if (t < off) red[t] += red[t + off];
        __syncthreads();
    }
    if (t < 32) {
        float v = red[t];
#pragma unroll
        for (int off = 16; off > 0; off >>= 1)
            v += __shfl_xor_sync(0xFFFFFFFFu, v, off);
        if (t == 0) g_sums[bd * 4 + ic] = v;
    }
}

__global__ void mse_kernel(const float* __restrict__ pred, float* __restrict__ out) {
    int t = threadIdx.x;
    float v = 0.0f;
    if (t < 16) {
        float s = 0.0f;
#pragma unroll
        for (int c = 0; c < 4; ++c) s += g_sums[t * 4 + c];
        float cham = s * (1.0f / (float)NPTS);
        float d = pred[t] - cham;
        v = d * d;
    }
#pragma unroll
    for (int off = 16; off > 0; off >>= 1)
        v += __shfl_xor_sync(0xFFFFFFFFu, v, off);
    if (t == 0) out[0] = v * (1.0f / 16.0f);
}

extern "C" void kernel_launch(void* const* d_in, const int* in_sizes, int n_in,
                              void* d_out, int out_size) {
    const float* pred         = (const float*)d_in[0];   // [8,2]
    const float* points       = (const float*)d_in[1];   // [8,3,4096]
    const float* points_trans = (const float*)d_in[2];   // [8,3,4096]
    float* out = (float*)d_out;

    chamfer_partial_kernel<<<8 * 2 * ISPLITS * SPLITS, TPB>>>(points, points_trans);
    chamfer_reduce_kernel<<<64, TPB>>>();
    mse_kernel<<<1, 32>>>(pred, out);
}